// round 2
// baseline (speedup 1.0000x reference)
#include <cuda_runtime.h>
#include <stdint.h>

#define NB_COUNT 32
#define DIM 128          // floats per row
#define VEC (DIM / 4)    // 32 float4 per row

// One warp per node. Lane l handles float4 column l.
// MLP-batched: 8 independent row gathers in flight per group, 4 groups.
__global__ __launch_bounds__(256) void sum_agg_kernel(
    const int* __restrict__ neighs,
    const float4* __restrict__ emb,   // [num_ids][32] float4
    float4* __restrict__ out,         // [node_count][32] float4
    int node_count)
{
    const int warp = (blockIdx.x * blockDim.x + threadIdx.x) >> 5;
    const int lane = threadIdx.x & 31;
    if (warp >= node_count) return;

    // Coalesced index load: lane l gets neighbor l of this node.
    const int my_idx = neighs[(size_t)warp * NB_COUNT + lane];

    float4 acc0 = make_float4(0.f, 0.f, 0.f, 0.f);
    float4 acc1 = make_float4(0.f, 0.f, 0.f, 0.f);
    float4 acc2 = make_float4(0.f, 0.f, 0.f, 0.f);
    float4 acc3 = make_float4(0.f, 0.f, 0.f, 0.f);

    #pragma unroll
    for (int g = 0; g < 4; ++g) {
        // Front-batch 8 independent gathers: all addresses depend only on
        // my_idx (shfl), so ptxas can issue all 8 LDG.128 back-to-back.
        float4 v[8];
        #pragma unroll
        for (int j = 0; j < 8; ++j) {
            const int r = __shfl_sync(0xffffffffu, my_idx, g * 8 + j);
            v[j] = __ldg(&emb[(size_t)r * VEC + lane]);
        }
        // 4 independent accumulator chains.
        acc0.x += v[0].x; acc0.y += v[0].y; acc0.z += v[0].z; acc0.w += v[0].w;
        acc1.x += v[1].x; acc1.y += v[1].y; acc1.z += v[1].z; acc1.w += v[1].w;
        acc2.x += v[2].x; acc2.y += v[2].y; acc2.z += v[2].z; acc2.w += v[2].w;
        acc3.x += v[3].x; acc3.y += v[3].y; acc3.z += v[3].z; acc3.w += v[3].w;
        acc0.x += v[4].x; acc0.y += v[4].y; acc0.z += v[4].z; acc0.w += v[4].w;
        acc1.x += v[5].x; acc1.y += v[5].y; acc1.z += v[5].z; acc1.w += v[5].w;
        acc2.x += v[6].x; acc2.y += v[6].y; acc2.z += v[6].z; acc2.w += v[6].w;
        acc3.x += v[7].x; acc3.y += v[7].y; acc3.z += v[7].z; acc3.w += v[7].w;
    }

    float4 r;
    r.x = (acc0.x + acc1.x) + (acc2.x + acc3.x);
    r.y = (acc0.y + acc1.y) + (acc2.y + acc3.y);
    r.z = (acc0.z + acc1.z) + (acc2.z + acc3.z);
    r.w = (acc0.w + acc1.w) + (acc2.w + acc3.w);
    out[(size_t)warp * VEC + lane] = r;
}

extern "C" void kernel_launch(void* const* d_in, const int* in_sizes, int n_in,
                              void* d_out, int out_size)
{
    // metadata order: neighs (int32), node_count (int scalar), emb_table (f32)
    const int* neighs = (const int*)d_in[0];
    const float4* emb = (const float4*)d_in[2];
    float4* out = (float4*)d_out;

    const int node_count = out_size / DIM;   // out is [node_count, 128] f32

    const int threads = 256;                  // 8 warps = 8 nodes per block
    const int blocks = (node_count * 32 + threads - 1) / threads;

    sum_agg_kernel<<<blocks, threads>>>(neighs, emb, out, node_count);
}